// round 12
// baseline (speedup 1.0000x reference)
#include <cuda_runtime.h>
#include <cuda_bf16.h>
#include <cuda_fp16.h>

#define TT 2000
#define NB 64
#define VV 1000
#define ROWS (TT * NB)
#define NEG_BIG (-1e30f)
#define FULLM 0xffffffffu

#define GRID_A 16000          // rowreduce blocks (8 rows each)
#define EPI_BLOCKS NB         // one epilogue block per n
#define EKITER 8              // ceil(TT/256)

// Scratch (no allocation allowed). n-major packed:
//   lo16 = argmax (V=1000 < 65536), hi16 = fp16 bits of maxlp.
__device__ unsigned g_packed[NB * TT];
__device__ int g_count;       // rowreduce-block release counter
__device__ int g_done;        // epilogue completion counter (for reset)

__global__ __launch_bounds__(256) void ctc_fused_kernel(
    const float* __restrict__ logits, const int* __restrict__ in_lens,
    float* __restrict__ out)
{
    const int bid  = blockIdx.x;
    const int tid  = threadIdx.x;
    const int lane = tid & 31;
    const int wid  = tid >> 5;

    if (bid < GRID_A) {
        // ---------------- rowreduce: warp-per-row over V=1000 ----------------
        const int row = bid * 8 + wid;               // row = t*NB + n
        const float4* __restrict__ p =
            reinterpret_cast<const float4*>(logits + (size_t)row * VV);

        float4 v[8];
#pragma unroll
        for (int j = 0; j < 8; j++) {
            int idx = lane + 32 * j;
            if (idx < 250) v[j] = p[idx];
            else           v[j] = make_float4(NEG_BIG, NEG_BIG, NEG_BIG, NEG_BIG);
        }

        float m = NEG_BIG; int am = 0;
#pragma unroll
        for (int j = 0; j < 8; j++) {
            int base = (lane + 32 * j) * 4;
            float x;
            x = v[j].x; if (x > m) { m = x; am = base;     }
            x = v[j].y; if (x > m) { m = x; am = base + 1; }
            x = v[j].z; if (x > m) { m = x; am = base + 2; }
            x = v[j].w; if (x > m) { m = x; am = base + 3; }
        }
#pragma unroll
        for (int off = 16; off; off >>= 1) {
            float om = __shfl_xor_sync(FULLM, m,  off);
            int   oa = __shfl_xor_sync(FULLM, am, off);
            if (om > m || (om == m && oa < am)) { m = om; am = oa; }
        }

        float s = 0.f;
#pragma unroll
        for (int j = 0; j < 8; j++) {
            s += __expf(v[j].x - m) + __expf(v[j].y - m)
               + __expf(v[j].z - m) + __expf(v[j].w - m);
        }
#pragma unroll
        for (int off = 16; off; off >>= 1)
            s += __shfl_xor_sync(FULLM, s, off);

        if (lane == 0) {
            float maxlp = -__logf(s);                // max - lse
            int t = row >> 6;                        // NB == 64
            int n = row & (NB - 1);
            unsigned hb = (unsigned)__half_as_ushort(__float2half_rn(maxlp));
            g_packed[n * TT + t] = (hb << 16) | (unsigned)am;
            out[NB + row] = (float)am;               // default paths (t-major)
        }

        __syncthreads();
        if (tid == 0) {
            // Release-ordered no-return reduction: orders this block's prior
            // global stores without any L1 flush (NOT a fence instruction).
            asm volatile("red.release.gpu.global.add.s32 [%0], %1;"
                         :: "l"(&g_count), "r"(1) : "memory");
        }
        return;
    }

    // ---------------- epilogue: block-per-n compaction + score ----------------
    __shared__ int   sh_a[256];
    __shared__ float sh_sc[8];

    const int n = bid - GRID_A;
    const int L = in_lens[n];                        // input; read before spin
    const unsigned* __restrict__ gp = g_packed + n * TT;

    if (tid == 0) {
        int c;
        do {
            asm volatile("ld.acquire.gpu.global.s32 %0, [%1];"
                         : "=r"(c) : "l"(&g_count));
            if (c >= GRID_A) break;
            __nanosleep(64);
        } while (true);
    }
    __syncthreads();   // acquire on tid0 + barrier -> whole block ordered

    // Prefetch all chunks via L2 (scratch is L2-warm; __ldcg avoids stale L1)
    unsigned v[EKITER];
#pragma unroll
    for (int k = 0; k < EKITER; k++) {
        int t = tid + 256 * k;
        v[k] = (t < TT) ? __ldcg(gp + t) : 0u;
    }

    float score = 0.f;
    int base  = 0;
    int carry = 0;

#pragma unroll
    for (int k = 0; k < EKITER; k++) {
        int   t = tid + 256 * k;
        int   a = (int)(v[k] & 0xffffu);
        float s = __half2float(__ushort_as_half((unsigned short)(v[k] >> 16)));

        sh_a[tid] = a;
        __syncthreads();

        int  aprev = (tid > 0) ? sh_a[tid - 1] : carry;
        bool valid = (t < TT);
        bool inm   = valid && (t < L);
        bool keep  = inm && (a != 0) && (a != aprev || t == 0);
        if (inm) score += s;

        unsigned bal = __ballot_sync(FULLM, keep);
        carry = sh_a[255];
        __syncthreads();                 // sh_a reads done before count overwrite
        if (lane == 0) sh_a[wid] = __popc(bal);
        __syncthreads();

        // Scan over 8 warp counts (lanes 0..7 of every warp, via shfl)
        int c0 = (lane < 8) ? sh_a[lane] : 0;
        int c  = c0;
#pragma unroll
        for (int off = 1; off < 8; off <<= 1) {
            int y = __shfl_up_sync(FULLM, c, off);
            if (lane >= off) c += y;
        }
        int total  = __shfl_sync(FULLM, c, 7);
        int prefix = base + __shfl_sync(FULLM, c - c0, wid);

        if (keep) {
            int pos = prefix + __popc(bal & ((1u << lane) - 1u));
            out[NB + pos * NB + n] = (float)a;       // overwrite compacted prefix
        }
        base += total;
        __syncthreads();                 // counts consumed before next round
    }

#pragma unroll
    for (int off = 16; off; off >>= 1)
        score += __shfl_xor_sync(FULLM, score, off);
    if (lane == 0) sh_sc[wid] = score;
    __syncthreads();

    if (tid == 0) {
        float tot = 0.f;
#pragma unroll
        for (int w = 0; w < 8; w++) tot += sh_sc[w];
        out[n] = tot;                                // score
        out[NB + TT * NB + n] = (float)base;         // out_lens
    }

    // Reset counters for the next graph replay (last epilogue block).
    __syncthreads();
    if (tid == 0) {
        if (atomicAdd(&g_done, 1) == EPI_BLOCKS - 1) {
            g_done = 0;
            atomicExch(&g_count, 0);
        }
    }
}

extern "C" void kernel_launch(void* const* d_in, const int* in_sizes, int n_in,
                              void* d_out, int out_size)
{
    const float* logits  = (const float*)d_in[0];
    const int*   in_lens = (const int*)d_in[1];
    float*       out     = (float*)d_out;

    ctc_fused_kernel<<<GRID_A + EPI_BLOCKS, 256>>>(logits, in_lens, out);
}